// round 5
// baseline (speedup 1.0000x reference)
#include <cuda_runtime.h>
#include <math.h>
#include <stdint.h>

#define N_NODES    50000
#define N_EDGES    600000
#define DIM        128
#define NUM_GRAPHS 512
#define GRID_GEMM  148
#define TILE       32
#define N_TILES    ((N_NODES + TILE - 1) / TILE)   // 1563
#define WSTRIDE    260     // words per combined weight row (260 % 32 == 4)
#define NSTRIDE    260     // words per staged node: 256 data + 4 pad

// Scratch (device globals: allocation inside kernel_launch is forbidden)
__device__ __align__(16) float g_agg[N_NODES * DIM];
__device__ float g_deg[N_NODES];
__device__ int   g_seg[NUM_GRAPHS];
__device__ float g_pmax[NUM_GRAPHS * DIM];
__device__ float g_psum[NUM_GRAPHS * DIM];

// ---- packed f32x2 helpers (sm_100a) ---------------------------------------
#define FMA2(acc, lo, hi, w) do {                                          \
    unsigned long long _ab;                                                \
    asm("mov.b64 %0, {%1, %2};" : "=l"(_ab) : "f"(lo), "f"(hi));           \
    asm("fma.rn.f32x2 %0, %1, %2, %0;" : "+l"(acc) : "l"(_ab), "l"(w));    \
} while (0)
#define PACK2(d, lo, hi) \
    asm("mov.b64 %0, {%1, %2};" : "=l"(d) : "f"(lo), "f"(hi))
#define UNPACK2(lo, hi, v) \
    asm("mov.b64 {%0, %1}, %2;" : "=f"(lo), "=f"(hi) : "l"(v))

// ---------------------------------------------------------------------------
// K0: zero agg + deg + pooled accumulators
// ---------------------------------------------------------------------------
__global__ void zero_kernel() {
    int i = blockIdx.x * blockDim.x + threadIdx.x;
    int stride = gridDim.x * blockDim.x;
    float4* p = reinterpret_cast<float4*>(g_agg);
    const int n4 = N_NODES * DIM / 4;
    for (int k = i; k < n4; k += stride) p[k] = make_float4(0.f, 0.f, 0.f, 0.f);
    for (int k = i; k < N_NODES; k += stride) g_deg[k] = 0.f;
    for (int k = i; k < NUM_GRAPHS * DIM; k += stride) {
        g_pmax[k] = 0.f;
        g_psum[k] = 0.f;
    }
}

// ---------------------------------------------------------------------------
// K1: segment starts from the sorted batch vector
// ---------------------------------------------------------------------------
__global__ void seg_kernel(const int* __restrict__ batch) {
    int i = blockIdx.x * blockDim.x + threadIdx.x;
    int stride = gridDim.x * blockDim.x;
    for (; i < N_NODES; i += stride) {
        if (i == 0 || batch[i] != batch[i - 1]) g_seg[batch[i]] = i;
    }
}

// ---------------------------------------------------------------------------
// K2: edge scatter. One warp per edge: gather emb[x_ids[src]] row (512B,
// coalesced), vector-reduce into agg[dst]. deg counted by lane 0.
// ---------------------------------------------------------------------------
__global__ void scatter_kernel(const int* __restrict__ ei,
                               const int* __restrict__ xids,
                               const float* __restrict__ emb) {
    int warp = (blockIdx.x * blockDim.x + threadIdx.x) >> 5;
    int lane = threadIdx.x & 31;
    if (warp >= N_EDGES) return;
    int src = __ldg(ei + warp);
    int dst = __ldg(ei + N_EDGES + warp);
    int id  = __ldg(xids + src);
    const float4* row = reinterpret_cast<const float4*>(emb + (size_t)id * DIM);
    float4 v = __ldg(row + lane);
    float* outp = g_agg + (size_t)dst * DIM + lane * 4;
    asm volatile("red.global.add.v4.f32 [%0], {%1,%2,%3,%4};"
                 :: "l"(outp), "f"(v.x), "f"(v.y), "f"(v.z), "f"(v.w)
                 : "memory");
    if (lane == 0) atomicAdd(g_deg + dst, 1.0f);
}

// ---------------------------------------------------------------------------
// K3 (persistent, 512 thr): streaming dual GEMM over flat 32-node tiles.
// Thread (c = t>>2, r = t&3): column c, nodes m*4+r (m=0..7). Weight LDS has
// 8 distinct addrs/warp (broadcast-dedup, 1 phase); data LDS has 4 distinct
// addrs/warp (1 phase). Pooling: shuffle-reduce over the 4 r lanes, then
// global atomicMax/atomicAdd per (graph, column) segment in the tile.
// ---------------------------------------------------------------------------
__global__ void __launch_bounds__(512, 1)
gemm_kernel(const int* __restrict__ xids,
            const int* __restrict__ batch,
            const float* __restrict__ emb,
            const float* __restrict__ Wl,
            const float* __restrict__ bl,
            const float* __restrict__ Wr) {
    extern __shared__ float smf[];
    float* sWc = smf;                               // [128][260] interleaved (Wl,Wr)
    float* sD  = smf + DIM * WSTRIDE;               // [32][260]  interleaved (a,x)
    int*   sB  = reinterpret_cast<int*>(sD + TILE * NSTRIDE);  // [32] batch ids

    const int t = threadIdx.x;
    const int c = t >> 2;       // output column
    const int r = t & 3;        // node sub-group

    // Combined weight tile: sWc[j][2k]=Wl[j][k], sWc[j][2k+1]=Wr[j][k]
    for (int idx = t; idx < DIM * DIM; idx += 512) {
        int j = idx >> 7, k = idx & 127;
        sWc[j * WSTRIDE + 2 * k]     = Wl[idx];
        sWc[j * WSTRIDE + 2 * k + 1] = Wr[idx];
    }
    const float blj = bl[c];
    const float4* wrow4 = reinterpret_cast<const float4*>(sWc + c * WSTRIDE);

    for (int tile = blockIdx.x; tile < N_TILES; tile += GRID_GEMM) {
        const int base = tile * TILE;
        const int nvalid = min(TILE, N_NODES - base);

        // Stage 32 nodes x 128 feats as (a, x) float2 pairs (coalesced LDG)
#pragma unroll
        for (int j = 0; j < 8; j++) {
            int i  = t + j * 512;
            int nl = i >> 7, f = i & 127;
            int n  = base + nl;
            float a = 0.f, x = 0.f;
            if (n < N_NODES) {
                float sc = __fdividef(1.f, fmaxf(g_deg[n], 1.f));
                a = g_agg[(size_t)n * DIM + f] * sc;
                x = emb[(size_t)__ldg(xids + n) * DIM + f];
            }
            *reinterpret_cast<float2*>(sD + nl * NSTRIDE + 2 * f) = make_float2(a, x);
        }
        if (t < TILE) {
            int n = base + t;
            sB[t] = (n < N_NODES) ? batch[n] : 0x7FFFFFFF;
        }
        __syncthreads();   // also orders sWc stores before first compute

        unsigned long long A[8];
#pragma unroll
        for (int m = 0; m < 8; m++) A[m] = 0ULL;

#pragma unroll 8
        for (int kk = 0; kk < DIM / 2; kk++) {
            float4 w4 = wrow4[kk];                 // (wl_k, wr_k, wl_k1, wr_k1)
            unsigned long long w2a, w2b;
            PACK2(w2a, w4.x, w4.y);
            PACK2(w2b, w4.z, w4.w);
#pragma unroll
            for (int m = 0; m < 8; m++) {
                const float4 d = *reinterpret_cast<const float4*>(
                    sD + (m * 4 + r) * NSTRIDE + 4 * kk);  // (a,x,a,x) feats 2kk,2kk+1
                FMA2(A[m], d.x, d.y, w2a);
                FMA2(A[m], d.z, d.w, w2b);
            }
        }

        // Epilogue: relu(h) + per-segment pooling
        float hv[8]; int gm[8];
#pragma unroll
        for (int m = 0; m < 8; m++) {
            float lo, hi;
            UNPACK2(lo, hi, A[m]);
            hv[m] = fmaxf(lo + hi + blj, 0.f);
            gm[m] = sB[m * 4 + r];
        }
        const int g0 = sB[0];
        const int g1 = sB[nvalid - 1];
        for (int g = g0; g <= g1; g++) {           // uniform per block (1-2 iters)
            float mx = 0.f, sme = 0.f;
#pragma unroll
            for (int m = 0; m < 8; m++) {
                if (gm[m] == g) { mx = fmaxf(mx, hv[m]); sme += hv[m]; }
            }
            mx  = fmaxf(mx, __shfl_xor_sync(0xFFFFFFFFu, mx, 1));
            mx  = fmaxf(mx, __shfl_xor_sync(0xFFFFFFFFu, mx, 2));
            sme += __shfl_xor_sync(0xFFFFFFFFu, sme, 1);
            sme += __shfl_xor_sync(0xFFFFFFFFu, sme, 2);
            if (r == 0) {
                // h >= 0: int-compare atomicMax is order-preserving, init 0
                atomicMax(reinterpret_cast<int*>(&g_pmax[g * DIM + c]),
                          __float_as_int(mx));
                atomicAdd(&g_psum[g * DIM + c], sme);
            }
        }
        __syncthreads();   // compute done before next tile overwrites sD/sB
    }
}

// ---------------------------------------------------------------------------
// K4: final linear + sigmoid. One block (128 thr) per graph.
// ---------------------------------------------------------------------------
__global__ void __launch_bounds__(128)
final_kernel(const float* __restrict__ w1, const float* __restrict__ b1,
             float* __restrict__ out) {
    __shared__ float sred[4];
    const int g = blockIdx.x;
    const int c = threadIdx.x;
    const int start = g_seg[g];
    const int end   = (g == NUM_GRAPHS - 1) ? N_NODES : g_seg[g + 1];
    const float cnt = (float)(end - start);
    float val = g_pmax[g * DIM + c] * w1[c]
              + (g_psum[g * DIM + c] / cnt) * w1[DIM + c];
#pragma unroll
    for (int off = 16; off > 0; off >>= 1)
        val += __shfl_down_sync(0xFFFFFFFFu, val, off);
    if ((c & 31) == 0) sred[c >> 5] = val;
    __syncthreads();
    if (c == 0) {
        float tot = sred[0] + sred[1] + sred[2] + sred[3] + b1[0];
        out[g] = 1.f / (1.f + expf(-tot));
    }
}

// ---------------------------------------------------------------------------
extern "C" void kernel_launch(void* const* d_in, const int* in_sizes, int n_in,
                              void* d_out, int out_size) {
    const int*   xids  = (const int*)d_in[0];
    const int*   ei    = (const int*)d_in[1];
    const int*   batch = (const int*)d_in[2];
    const float* emb   = (const float*)d_in[3];
    const float* Wl    = (const float*)d_in[4];
    const float* bl    = (const float*)d_in[5];
    const float* Wr    = (const float*)d_in[6];
    const float* w1    = (const float*)d_in[7];
    const float* b1    = (const float*)d_in[8];
    float*       out   = (float*)d_out;

    zero_kernel<<<2048, 256>>>();
    seg_kernel<<<256, 256>>>(batch);
    {
        long long threads = (long long)N_EDGES * 32;
        int blocks = (int)((threads + 255) / 256);
        scatter_kernel<<<blocks, 256>>>(ei, xids, emb);
    }
    size_t smem = (size_t)(DIM * WSTRIDE + TILE * NSTRIDE) * sizeof(float)
                + TILE * sizeof(int);
    static int attr_set = 0;
    if (!attr_set) {
        cudaFuncSetAttribute(gemm_kernel,
                             cudaFuncAttributeMaxDynamicSharedMemorySize, (int)smem);
        attr_set = 1;
    }
    gemm_kernel<<<GRID_GEMM, 512, smem>>>(xids, batch, emb, Wl, bl, Wr);
    final_kernel<<<NUM_GRAPHS, 128>>>(w1, b1, out);
}

// round 6
// speedup vs baseline: 1.2464x; 1.2464x over previous
#include <cuda_runtime.h>
#include <math.h>
#include <stdint.h>

#define N_NODES    50000
#define N_EDGES    600000
#define DIM        128
#define NUM_GRAPHS 512
#define GRID_GEMM  148
#define TILE       32
#define N_TILES    ((N_NODES + TILE - 1) / TILE)   // 1563
#define WSTRIDE    516     // floats per column-PAIR weight row (516 % 32 == 4)
#define NSTRIDE    260     // floats per staged node (260 % 32 == 4)

// Scratch (device globals: allocation inside kernel_launch is forbidden)
__device__ __align__(16) float g_agg[N_NODES * DIM];
__device__ float g_deg[N_NODES];
__device__ int   g_seg[NUM_GRAPHS];
__device__ float g_pmax[NUM_GRAPHS * DIM];
__device__ float g_psum[NUM_GRAPHS * DIM];

// ---- packed f32x2 helpers (sm_100a) ---------------------------------------
#define FMA2(acc, lo, hi, w) do {                                          \
    unsigned long long _ab;                                                \
    asm("mov.b64 %0, {%1, %2};" : "=l"(_ab) : "f"(lo), "f"(hi));           \
    asm("fma.rn.f32x2 %0, %1, %2, %0;" : "+l"(acc) : "l"(_ab), "l"(w));    \
} while (0)
#define PACK2(d, lo, hi) \
    asm("mov.b64 %0, {%1, %2};" : "=l"(d) : "f"(lo), "f"(hi))
#define UNPACK2(lo, hi, v) \
    asm("mov.b64 {%0, %1}, %2;" : "=f"(lo), "=f"(hi) : "l"(v))

// ---------------------------------------------------------------------------
// K0: zero agg + deg + pooled accumulators
// ---------------------------------------------------------------------------
__global__ void zero_kernel() {
    int i = blockIdx.x * blockDim.x + threadIdx.x;
    int stride = gridDim.x * blockDim.x;
    float4* p = reinterpret_cast<float4*>(g_agg);
    const int n4 = N_NODES * DIM / 4;
    for (int k = i; k < n4; k += stride) p[k] = make_float4(0.f, 0.f, 0.f, 0.f);
    for (int k = i; k < N_NODES; k += stride) g_deg[k] = 0.f;
    for (int k = i; k < NUM_GRAPHS * DIM; k += stride) {
        g_pmax[k] = 0.f;
        g_psum[k] = 0.f;
    }
}

// ---------------------------------------------------------------------------
// K1: segment starts from the sorted batch vector
// ---------------------------------------------------------------------------
__global__ void seg_kernel(const int* __restrict__ batch) {
    int i = blockIdx.x * blockDim.x + threadIdx.x;
    int stride = gridDim.x * blockDim.x;
    for (; i < N_NODES; i += stride) {
        if (i == 0 || batch[i] != batch[i - 1]) g_seg[batch[i]] = i;
    }
}

// ---------------------------------------------------------------------------
// K2: edge scatter. One warp per edge: gather emb[x_ids[src]] row (512B,
// coalesced), vector-reduce into agg[dst]. deg counted by lane 0.
// ---------------------------------------------------------------------------
__global__ void scatter_kernel(const int* __restrict__ ei,
                               const int* __restrict__ xids,
                               const float* __restrict__ emb) {
    int warp = (blockIdx.x * blockDim.x + threadIdx.x) >> 5;
    int lane = threadIdx.x & 31;
    if (warp >= N_EDGES) return;
    int src = __ldg(ei + warp);
    int dst = __ldg(ei + N_EDGES + warp);
    int id  = __ldg(xids + src);
    const float4* row = reinterpret_cast<const float4*>(emb + (size_t)id * DIM);
    float4 v = __ldg(row + lane);
    float* outp = g_agg + (size_t)dst * DIM + lane * 4;
    asm volatile("red.global.add.v4.f32 [%0], {%1,%2,%3,%4};"
                 :: "l"(outp), "f"(v.x), "f"(v.y), "f"(v.z), "f"(v.w)
                 : "memory");
    if (lane == 0) atomicAdd(g_deg + dst, 1.0f);
}

// ---------------------------------------------------------------------------
// K3 (persistent, 256 thr): streaming dual GEMM over flat 32-node tiles.
// Thread (cq = t>>2, r = t&3): columns {2cq, 2cq+1}, nodes m*4+r (m=0..7)
// => 16 outputs/thread, 32 acc regs, ~180 regs of headroom for ptxas to
// front-batch the 10 LDS.128 per kk-iter (this was the round-3 failure).
// Weight row per cq: 516-float stride (=4 mod 32, 1-phase dedup'd LDS).
// ---------------------------------------------------------------------------
__global__ void __launch_bounds__(256, 1)
gemm_kernel(const int* __restrict__ xids,
            const int* __restrict__ batch,
            const float* __restrict__ emb,
            const float* __restrict__ Wl,
            const float* __restrict__ bl,
            const float* __restrict__ Wr) {
    extern __shared__ float smf[];
    float* sW = smf;                                    // [64][516]
    float* sD = smf + 64 * WSTRIDE;                     // [32][260]
    int*   sB = reinterpret_cast<int*>(sD + TILE * NSTRIDE);  // [32]

    const int t  = threadIdx.x;
    const int cq = t >> 2;      // column pair 0..63
    const int r  = t & 3;       // node sub-group
    const int c0 = 2 * cq, c1 = 2 * cq + 1;

    // Weight tile: sW[q][4k..4k+3] = (Wl[2q][k], Wr[2q][k], Wl[2q+1][k], Wr[2q+1][k])
    for (int idx = t; idx < 64 * DIM; idx += 256) {
        int q = idx >> 7, k = idx & 127;
        float4 v;
        v.x = Wl[(2 * q) * DIM + k];
        v.y = Wr[(2 * q) * DIM + k];
        v.z = Wl[(2 * q + 1) * DIM + k];
        v.w = Wr[(2 * q + 1) * DIM + k];
        *reinterpret_cast<float4*>(sW + q * WSTRIDE + 4 * k) = v;
    }
    const float bl0 = bl[c0];
    const float bl1 = bl[c1];
    const float4* wrow = reinterpret_cast<const float4*>(sW + cq * WSTRIDE);

    for (int tile = blockIdx.x; tile < N_TILES; tile += GRID_GEMM) {
        const int base = tile * TILE;
        const int nvalid = min(TILE, N_NODES - base);

        // Stage 32 nodes x 128 feats as (a, x) pairs (coalesced LDG, 16/thread)
#pragma unroll
        for (int j = 0; j < 16; j++) {
            int i  = t + j * 256;
            int nl = i >> 7, f = i & 127;
            int n  = base + nl;
            float a = 0.f, x = 0.f;
            if (n < N_NODES) {
                float sc = __fdividef(1.f, fmaxf(g_deg[n], 1.f));
                a = g_agg[(size_t)n * DIM + f] * sc;
                x = emb[(size_t)__ldg(xids + n) * DIM + f];
            }
            *reinterpret_cast<float2*>(sD + nl * NSTRIDE + 2 * f) = make_float2(a, x);
        }
        if (t < TILE) {
            int n = base + t;
            sB[t] = (n < N_NODES) ? batch[n] : 0x7FFFFFFF;
        }
        __syncthreads();   // also orders sW stores before first compute

        unsigned long long A0[8], A1[8];
#pragma unroll
        for (int m = 0; m < 8; m++) { A0[m] = 0ULL; A1[m] = 0ULL; }

#pragma unroll 2
        for (int kk = 0; kk < DIM / 2; kk++) {          // 2 k-features per iter
            float4 wa = wrow[2 * kk];                   // k=2kk:   (wl0,wr0,wl1,wr1)
            float4 wb = wrow[2 * kk + 1];               // k=2kk+1: (wl0,wr0,wl1,wr1)
            unsigned long long w0a, w0b, w1a, w1b;
            PACK2(w0a, wa.x, wa.y);  PACK2(w0b, wa.z, wa.w);
            PACK2(w1a, wb.x, wb.y);  PACK2(w1b, wb.z, wb.w);
#pragma unroll
            for (int m = 0; m < 8; m++) {
                const float4 d = *reinterpret_cast<const float4*>(
                    sD + (m * 4 + r) * NSTRIDE + 4 * kk);  // (a,x,a,x) feats 2kk,2kk+1
                FMA2(A0[m], d.x, d.y, w0a);
                FMA2(A0[m], d.z, d.w, w1a);
                FMA2(A1[m], d.x, d.y, w0b);
                FMA2(A1[m], d.z, d.w, w1b);
            }
        }

        // Epilogue: relu + per-segment pooling (shuffle over r lanes + atomics)
        float hv0[8], hv1[8]; int gm[8];
#pragma unroll
        for (int m = 0; m < 8; m++) {
            float lo, hi;
            UNPACK2(lo, hi, A0[m]); hv0[m] = fmaxf(lo + hi + bl0, 0.f);
            UNPACK2(lo, hi, A1[m]); hv1[m] = fmaxf(lo + hi + bl1, 0.f);
            gm[m] = sB[m * 4 + r];
        }
        const int g0 = sB[0];
        const int g1 = sB[nvalid - 1];
        for (int g = g0; g <= g1; g++) {       // uniform per block (1-2 iters)
            float m0 = 0.f, s0 = 0.f, m1 = 0.f, s1 = 0.f;
#pragma unroll
            for (int m = 0; m < 8; m++) {
                if (gm[m] == g) {
                    m0 = fmaxf(m0, hv0[m]); s0 += hv0[m];
                    m1 = fmaxf(m1, hv1[m]); s1 += hv1[m];
                }
            }
            m0  = fmaxf(m0, __shfl_xor_sync(0xFFFFFFFFu, m0, 1));
            m0  = fmaxf(m0, __shfl_xor_sync(0xFFFFFFFFu, m0, 2));
            m1  = fmaxf(m1, __shfl_xor_sync(0xFFFFFFFFu, m1, 1));
            m1  = fmaxf(m1, __shfl_xor_sync(0xFFFFFFFFu, m1, 2));
            s0 += __shfl_xor_sync(0xFFFFFFFFu, s0, 1);
            s0 += __shfl_xor_sync(0xFFFFFFFFu, s0, 2);
            s1 += __shfl_xor_sync(0xFFFFFFFFu, s1, 1);
            s1 += __shfl_xor_sync(0xFFFFFFFFu, s1, 2);
            if (r == 0) {
                // h >= 0: int-compare atomicMax is order-preserving, init 0
                atomicMax(reinterpret_cast<int*>(&g_pmax[g * DIM + c0]),
                          __float_as_int(m0));
                atomicAdd(&g_psum[g * DIM + c0], s0);
                atomicMax(reinterpret_cast<int*>(&g_pmax[g * DIM + c1]),
                          __float_as_int(m1));
                atomicAdd(&g_psum[g * DIM + c1], s1);
            }
        }
        __syncthreads();   // compute done before next tile overwrites sD/sB
    }
}

// ---------------------------------------------------------------------------
// K4: final linear + sigmoid. One block (128 thr) per graph.
// ---------------------------------------------------------------------------
__global__ void __launch_bounds__(128)
final_kernel(const float* __restrict__ w1, const float* __restrict__ b1,
             float* __restrict__ out) {
    __shared__ float sred[4];
    const int g = blockIdx.x;
    const int c = threadIdx.x;
    const int start = g_seg[g];
    const int end   = (g == NUM_GRAPHS - 1) ? N_NODES : g_seg[g + 1];
    const float cnt = (float)(end - start);
    float val = g_pmax[g * DIM + c] * w1[c]
              + (g_psum[g * DIM + c] / cnt) * w1[DIM + c];
#pragma unroll
    for (int off = 16; off > 0; off >>= 1)
        val += __shfl_down_sync(0xFFFFFFFFu, val, off);
    if ((c & 31) == 0) sred[c >> 5] = val;
    __syncthreads();
    if (c == 0) {
        float tot = sred[0] + sred[1] + sred[2] + sred[3] + b1[0];
        out[g] = 1.f / (1.f + expf(-tot));
    }
}

// ---------------------------------------------------------------------------
extern "C" void kernel_launch(void* const* d_in, const int* in_sizes, int n_in,
                              void* d_out, int out_size) {
    const int*   xids  = (const int*)d_in[0];
    const int*   ei    = (const int*)d_in[1];
    const int*   batch = (const int*)d_in[2];
    const float* emb   = (const float*)d_in[3];
    const float* Wl    = (const float*)d_in[4];
    const float* bl    = (const float*)d_in[5];
    const float* Wr    = (const float*)d_in[6];
    const float* w1    = (const float*)d_in[7];
    const float* b1    = (const float*)d_in[8];
    float*       out   = (float*)d_out;

    zero_kernel<<<2048, 256>>>();
    seg_kernel<<<256, 256>>>(batch);
    {
        long long threads = (long long)N_EDGES * 32;
        int blocks = (int)((threads + 255) / 256);
        scatter_kernel<<<blocks, 256>>>(ei, xids, emb);
    }
    size_t smem = (size_t)(64 * WSTRIDE + TILE * NSTRIDE) * sizeof(float)
                + TILE * sizeof(int);
    static int attr_set = 0;
    if (!attr_set) {
        cudaFuncSetAttribute(gemm_kernel,
                             cudaFuncAttributeMaxDynamicSharedMemorySize, (int)smem);
        attr_set = 1;
    }
    gemm_kernel<<<GRID_GEMM, 256, smem>>>(xids, batch, emb, Wl, bl, Wr);
    final_kernel<<<NUM_GRAPHS, 128>>>(w1, b1, out);
}

// round 11
// speedup vs baseline: 2.3414x; 1.8785x over previous
#include <cuda_runtime.h>
#include <cuda_bf16.h>
#include <math.h>
#include <stdint.h>

#define N_NODES    50000
#define N_EDGES    600000
#define DIM        128
#define NUM_GRAPHS 512
#define TILE_M     128
#define N_TILES    ((N_NODES + TILE_M - 1) / TILE_M)   // 391
#define GRID_GEMM  148
#define ROWB       528        // bytes/row: 256 bf16 = 512 data + 16 pad; 528%128==16 -> LDSM conflict-free
#define HSTRIDE    130        // floats per h row
#define TILE_B     (128 * ROWB)             // 67584 B per operand tile
// dynamic smem regions (within 1024-aligned base)
#define OFF_W      0
#define OFF_A      (TILE_B)
#define OFF_H      (2 * TILE_B)
#define SMEM_DYN   (OFF_H + 128 * HSTRIDE * 4 + 1024)   // ~198 KB < 227 KB cap

// Scratch (device globals: allocation inside kernel_launch is forbidden)
__device__ __align__(16) float g_agg[N_NODES * DIM];
__device__ float g_deg[N_NODES];
__device__ int   g_seg[NUM_GRAPHS];
__device__ float g_pmax[NUM_GRAPHS * DIM];
__device__ float g_psum[NUM_GRAPHS * DIM];

// ---- warp-MMA helpers (sm_80-era PTX, valid for compute_100) ---------------
__device__ __forceinline__ uint32_t smem_u32(const void* p) {
    uint32_t a;
    asm("{ .reg .u64 t; cvta.to.shared.u64 t, %1; cvt.u32.u64 %0, t; }"
        : "=r"(a) : "l"(p));
    return a;
}
__device__ __forceinline__ void ldsm_x4(uint32_t* r, uint32_t addr) {
    asm volatile("ldmatrix.sync.aligned.m8n8.x4.shared.b16 {%0,%1,%2,%3}, [%4];"
                 : "=r"(r[0]), "=r"(r[1]), "=r"(r[2]), "=r"(r[3]) : "r"(addr));
}
__device__ __forceinline__ void ldsm_x2(uint32_t* r, uint32_t addr) {
    asm volatile("ldmatrix.sync.aligned.m8n8.x2.shared.b16 {%0,%1}, [%2];"
                 : "=r"(r[0]), "=r"(r[1]) : "r"(addr));
}
__device__ __forceinline__ void mma16816(float* c, const uint32_t* a, const uint32_t* b) {
    asm volatile(
        "mma.sync.aligned.m16n8k16.row.col.f32.bf16.bf16.f32 "
        "{%0,%1,%2,%3}, {%4,%5,%6,%7}, {%8,%9}, {%0,%1,%2,%3};"
        : "+f"(c[0]), "+f"(c[1]), "+f"(c[2]), "+f"(c[3])
        : "r"(a[0]), "r"(a[1]), "r"(a[2]), "r"(a[3]), "r"(b[0]), "r"(b[1]));
}
__device__ __forceinline__ uint4 pack_bf16x8(const float* f) {
    __nv_bfloat162 h0 = __float22bfloat162_rn(make_float2(f[0], f[1]));
    __nv_bfloat162 h1 = __float22bfloat162_rn(make_float2(f[2], f[3]));
    __nv_bfloat162 h2 = __float22bfloat162_rn(make_float2(f[4], f[5]));
    __nv_bfloat162 h3 = __float22bfloat162_rn(make_float2(f[6], f[7]));
    uint4 u;
    u.x = *reinterpret_cast<uint32_t*>(&h0);
    u.y = *reinterpret_cast<uint32_t*>(&h1);
    u.z = *reinterpret_cast<uint32_t*>(&h2);
    u.w = *reinterpret_cast<uint32_t*>(&h3);
    return u;
}

// ---------------------------------------------------------------------------
__global__ void zero_kernel() {
    int i = blockIdx.x * blockDim.x + threadIdx.x;
    int stride = gridDim.x * blockDim.x;
    float4* p = reinterpret_cast<float4*>(g_agg);
    const int n4 = N_NODES * DIM / 4;
    for (int k = i; k < n4; k += stride) p[k] = make_float4(0.f, 0.f, 0.f, 0.f);
    for (int k = i; k < N_NODES; k += stride) g_deg[k] = 0.f;
    for (int k = i; k < NUM_GRAPHS * DIM; k += stride) {
        g_pmax[k] = 0.f;
        g_psum[k] = 0.f;
    }
}

__global__ void seg_kernel(const int* __restrict__ batch) {
    int i = blockIdx.x * blockDim.x + threadIdx.x;
    int stride = gridDim.x * blockDim.x;
    for (; i < N_NODES; i += stride) {
        if (i == 0 || batch[i] != batch[i - 1]) g_seg[batch[i]] = i;
    }
}

__global__ void scatter_kernel(const int* __restrict__ ei,
                               const int* __restrict__ xids,
                               const float* __restrict__ emb) {
    int warp = (blockIdx.x * blockDim.x + threadIdx.x) >> 5;
    int lane = threadIdx.x & 31;
    if (warp >= N_EDGES) return;
    int src = __ldg(ei + warp);
    int dst = __ldg(ei + N_EDGES + warp);
    int id  = __ldg(xids + src);
    const float4* row = reinterpret_cast<const float4*>(emb + (size_t)id * DIM);
    float4 v = __ldg(row + lane);
    float* outp = g_agg + (size_t)dst * DIM + lane * 4;
    asm volatile("red.global.add.v4.f32 [%0], {%1,%2,%3,%4};"
                 :: "l"(outp), "f"(v.x), "f"(v.y), "f"(v.z), "f"(v.w)
                 : "memory");
    if (lane == 0) atomicAdd(g_deg + dst, 1.0f);
}

// ---------------------------------------------------------------------------
// K3: warp-MMA GEMM.  h(50000x128) = [aggn | x](50000x256) @ [Wl | Wr]^T,
// bf16 mma.sync m16n8k16, tile M=128/N=128/K=256 per block. 8 warps: warp w
// owns rows w*16..w*16+15 x all 128 cols. Row stride 528 B (512 data + pad).
// Epilogue: bias+relu -> smem h tile -> segmented pooling via atomics.
// ---------------------------------------------------------------------------
__global__ void __launch_bounds__(256, 1)
mma_kernel(const int* __restrict__ xids,
           const int* __restrict__ batch,
           const float* __restrict__ emb,
           const float* __restrict__ Wl,
           const float* __restrict__ bl,
           const float* __restrict__ Wr) {
    extern __shared__ char dyn[];
    char* base = (char*)(((uintptr_t)dyn + 1023) & ~(uintptr_t)1023);
    char*  sW = base + OFF_W;            // [128 n][256 k] bf16, row stride 528B
    char*  sA = base + OFF_A;            // [128 m][256 k] bf16, row stride 528B
    float* sH = reinterpret_cast<float*>(base + OFF_H);   // [128][130]

    __shared__ float s_bl[DIM];
    __shared__ int   s_bid[TILE_M];

    const int t    = threadIdx.x;
    const int wid  = t >> 5;
    const int lane = t & 31;

    if (t < DIM) s_bl[t] = bl[t];

    // Stage combined weights [Wl | Wr] (once per block): row n, k chunk ck
    for (int j = 0; j < 16; j++) {
        int chunk = t + j * 256;
        int n  = chunk >> 5;             // output column 0..127
        int ck = (chunk & 31) * 8;       // k chunk start (0..248)
        const float* src = (ck < DIM) ? (Wl + n * DIM + ck)
                                      : (Wr + n * DIM + (ck - DIM));
        float f[8];
        *reinterpret_cast<float4*>(f)     = *reinterpret_cast<const float4*>(src);
        *reinterpret_cast<float4*>(f + 4) = *reinterpret_cast<const float4*>(src + 4);
        *reinterpret_cast<uint4*>(sW + n * ROWB + ck * 2) = pack_bf16x8(f);
    }

    const uint32_t sA_base = smem_u32(sA);
    const uint32_t sW_base = smem_u32(sW);
    // ldmatrix lane address components
    const uint32_t a_lane_off = (uint32_t)((wid * 16 + (lane & 15)) * ROWB
                                           + ((lane >> 4) * 8) * 2);
    const uint32_t b_lane_off = (uint32_t)((lane & 7) * ROWB
                                           + ((lane >> 3) & 1) * 16);

    for (int tile = blockIdx.x; tile < N_TILES; tile += GRID_GEMM) {
        const int tbase = tile * TILE_M;

        // ---- stage A tile: [aggn | x] -> bf16 ----
        for (int j = 0; j < 16; j++) {
            int chunk = t + j * 256;
            int r  = chunk >> 5;
            int ck = (chunk & 31) * 8;
            int n  = tbase + r;
            float f[8];
#pragma unroll
            for (int i = 0; i < 8; i++) f[i] = 0.f;
            if (n < N_NODES) {
                if (ck < DIM) {
                    float sc = __fdividef(1.f, fmaxf(g_deg[n], 1.f));
                    const float4* s4 = reinterpret_cast<const float4*>(
                        g_agg + (size_t)n * DIM + ck);
                    *reinterpret_cast<float4*>(f)     = s4[0];
                    *reinterpret_cast<float4*>(f + 4) = s4[1];
#pragma unroll
                    for (int i = 0; i < 8; i++) f[i] *= sc;
                } else {
                    int id = __ldg(xids + n);
                    const float4* s4 = reinterpret_cast<const float4*>(
                        emb + (size_t)id * DIM + (ck - DIM));
                    *reinterpret_cast<float4*>(f)     = s4[0];
                    *reinterpret_cast<float4*>(f + 4) = s4[1];
                }
            }
            *reinterpret_cast<uint4*>(sA + r * ROWB + ck * 2) = pack_bf16x8(f);
        }
        if (t < TILE_M)
            s_bid[t] = (tbase + t < N_NODES) ? batch[tbase + t] : -1;
        __syncthreads();

        // ---- MMA mainloop: 16 k16 steps x 16 n-tiles ----
        float acc[16][4];
#pragma unroll
        for (int n = 0; n < 16; n++)
#pragma unroll
            for (int i = 0; i < 4; i++) acc[n][i] = 0.f;

        for (int kk = 0; kk < 16; kk++) {
            uint32_t a[4];
            ldsm_x4(a, sA_base + a_lane_off + kk * 32);
            uint32_t bf[16][2];
#pragma unroll
            for (int n = 0; n < 16; n++)
                ldsm_x2(bf[n], sW_base + (uint32_t)(n * 8 * ROWB) + b_lane_off
                               + kk * 32);
#pragma unroll
            for (int n = 0; n < 16; n++)
                mma16816(acc[n], a, bf[n]);
        }

        // ---- epilogue: bias + relu -> sH ----
        {
            int row  = wid * 16 + (lane >> 2);
            int colb = (lane & 3) * 2;
#pragma unroll
            for (int n = 0; n < 16; n++) {
                int col = n * 8 + colb;
                float b0 = s_bl[col], b1 = s_bl[col + 1];
                *reinterpret_cast<float2*>(sH + row * HSTRIDE + col) =
                    make_float2(fmaxf(acc[n][0] + b0, 0.f),
                                fmaxf(acc[n][1] + b1, 0.f));
                *reinterpret_cast<float2*>(sH + (row + 8) * HSTRIDE + col) =
                    make_float2(fmaxf(acc[n][2] + b0, 0.f),
                                fmaxf(acc[n][3] + b1, 0.f));
            }
        }
        __syncthreads();

        // ---- segmented pooling over rows; atomics per (graph, col) ----
        {
            int c = t & 127;
            int half = t >> 7;
            int gprev = -2;
            float mx = 0.f, sm = 0.f;
            for (int r = half * 64; r < half * 64 + 64; r++) {
                int gid = s_bid[r];
                float hv = sH[r * HSTRIDE + c];
                if (gid != gprev) {
                    if (gprev >= 0) {
                        atomicMax(reinterpret_cast<int*>(&g_pmax[gprev * DIM + c]),
                                  __float_as_int(mx));
                        atomicAdd(&g_psum[gprev * DIM + c], sm);
                    }
                    gprev = gid; mx = hv; sm = hv;
                } else {
                    mx = fmaxf(mx, hv); sm += hv;
                }
            }
            if (gprev >= 0) {
                atomicMax(reinterpret_cast<int*>(&g_pmax[gprev * DIM + c]),
                          __float_as_int(mx));
                atomicAdd(&g_psum[gprev * DIM + c], sm);
            }
        }
        __syncthreads();   // sA/sH reuse safe for next tile
    }
}

// ---------------------------------------------------------------------------
__global__ void __launch_bounds__(128)
final_kernel(const float* __restrict__ w1, const float* __restrict__ b1,
             float* __restrict__ out) {
    __shared__ float sred[4];
    const int g = blockIdx.x;
    const int c = threadIdx.x;
    const int start = g_seg[g];
    const int end   = (g == NUM_GRAPHS - 1) ? N_NODES : g_seg[g + 1];
    const float cnt = (float)(end - start);
    float val = g_pmax[g * DIM + c] * w1[c]
              + (g_psum[g * DIM + c] / cnt) * w1[DIM + c];
#pragma unroll
    for (int off = 16; off > 0; off >>= 1)
        val += __shfl_down_sync(0xFFFFFFFFu, val, off);
    if ((c & 31) == 0) sred[c >> 5] = val;
    __syncthreads();
    if (c == 0) {
        float tot = sred[0] + sred[1] + sred[2] + sred[3] + b1[0];
        out[g] = 1.f / (1.f + expf(-tot));
    }
}

// ---------------------------------------------------------------------------
extern "C" void kernel_launch(void* const* d_in, const int* in_sizes, int n_in,
                              void* d_out, int out_size) {
    const int*   xids  = (const int*)d_in[0];
    const int*   ei    = (const int*)d_in[1];
    const int*   batch = (const int*)d_in[2];
    const float* emb   = (const float*)d_in[3];
    const float* Wl    = (const float*)d_in[4];
    const float* bl    = (const float*)d_in[5];
    const float* Wr    = (const float*)d_in[6];
    const float* w1    = (const float*)d_in[7];
    const float* b1    = (const float*)d_in[8];
    float*       out   = (float*)d_out;

    zero_kernel<<<2048, 256>>>();
    seg_kernel<<<256, 256>>>(batch);
    {
        long long threads = (long long)N_EDGES * 32;
        int blocks = (int)((threads + 255) / 256);
        scatter_kernel<<<blocks, 256>>>(ei, xids, emb);
    }
    static int attr_set = 0;
    if (!attr_set) {
        cudaFuncSetAttribute(mma_kernel,
                             cudaFuncAttributeMaxDynamicSharedMemorySize, SMEM_DYN);
        attr_set = 1;
    }
    mma_kernel<<<GRID_GEMM, 256, SMEM_DYN>>>(xids, batch, emb, Wl, bl, Wr);
    final_kernel<<<NUM_GRAPHS, 128>>>(w1, b1, out);
}

// round 12
// speedup vs baseline: 2.4166x; 1.0321x over previous
#include <cuda_runtime.h>
#include <cuda_bf16.h>
#include <math.h>
#include <stdint.h>

#define N_NODES    50000
#define N_EDGES    600000
#define DIM        128
#define NUM_GRAPHS 512
#define TILE_M     64
#define N_TILES    ((N_NODES + TILE_M - 1) / TILE_M)   // 782
#define GRID_GEMM  296        // 2 blocks per SM
#define ROWB       528        // bytes/row: 256 bf16 = 512 data + 16 pad; LDSM conflict-free
#define OFF_W      0
#define OFF_A      (128 * ROWB)                 // W: 128 rows
#define SMEM_DYN   (OFF_A + TILE_M * ROWB)      // 67584 + 33792 = 101376 B

// Scratch (device globals: allocation inside kernel_launch is forbidden)
__device__ __align__(16) float g_agg[N_NODES * DIM];
__device__ float g_deg[N_NODES];
__device__ int   g_seg[NUM_GRAPHS];
__device__ float g_pmax[NUM_GRAPHS * DIM];
__device__ float g_psum[NUM_GRAPHS * DIM];

// ---- warp-MMA helpers (sm_80-era PTX, valid for compute_100) ---------------
__device__ __forceinline__ uint32_t smem_u32(const void* p) {
    uint32_t a;
    asm("{ .reg .u64 t; cvta.to.shared.u64 t, %1; cvt.u32.u64 %0, t; }"
        : "=r"(a) : "l"(p));
    return a;
}
__device__ __forceinline__ void ldsm_x4(uint32_t* r, uint32_t addr) {
    asm volatile("ldmatrix.sync.aligned.m8n8.x4.shared.b16 {%0,%1,%2,%3}, [%4];"
                 : "=r"(r[0]), "=r"(r[1]), "=r"(r[2]), "=r"(r[3]) : "r"(addr));
}
__device__ __forceinline__ void ldsm_x2(uint32_t* r, uint32_t addr) {
    asm volatile("ldmatrix.sync.aligned.m8n8.x2.shared.b16 {%0,%1}, [%2];"
                 : "=r"(r[0]), "=r"(r[1]) : "r"(addr));
}
__device__ __forceinline__ void mma16816(float* c, const uint32_t* a, const uint32_t* b) {
    asm volatile(
        "mma.sync.aligned.m16n8k16.row.col.f32.bf16.bf16.f32 "
        "{%0,%1,%2,%3}, {%4,%5,%6,%7}, {%8,%9}, {%0,%1,%2,%3};"
        : "+f"(c[0]), "+f"(c[1]), "+f"(c[2]), "+f"(c[3])
        : "r"(a[0]), "r"(a[1]), "r"(a[2]), "r"(a[3]), "r"(b[0]), "r"(b[1]));
}
__device__ __forceinline__ uint4 pack_bf16x8(const float* f) {
    __nv_bfloat162 h0 = __float22bfloat162_rn(make_float2(f[0], f[1]));
    __nv_bfloat162 h1 = __float22bfloat162_rn(make_float2(f[2], f[3]));
    __nv_bfloat162 h2 = __float22bfloat162_rn(make_float2(f[4], f[5]));
    __nv_bfloat162 h3 = __float22bfloat162_rn(make_float2(f[6], f[7]));
    uint4 u;
    u.x = *reinterpret_cast<uint32_t*>(&h0);
    u.y = *reinterpret_cast<uint32_t*>(&h1);
    u.z = *reinterpret_cast<uint32_t*>(&h2);
    u.w = *reinterpret_cast<uint32_t*>(&h3);
    return u;
}

// ---------------------------------------------------------------------------
__global__ void zero_kernel() {
    int i = blockIdx.x * blockDim.x + threadIdx.x;
    int stride = gridDim.x * blockDim.x;
    float4* p = reinterpret_cast<float4*>(g_agg);
    const int n4 = N_NODES * DIM / 4;
    for (int k = i; k < n4; k += stride) p[k] = make_float4(0.f, 0.f, 0.f, 0.f);
    for (int k = i; k < N_NODES; k += stride) g_deg[k] = 0.f;
    for (int k = i; k < NUM_GRAPHS * DIM; k += stride) {
        g_pmax[k] = 0.f;
        g_psum[k] = 0.f;
    }
}

__global__ void seg_kernel(const int* __restrict__ batch) {
    int i = blockIdx.x * blockDim.x + threadIdx.x;
    int stride = gridDim.x * blockDim.x;
    for (; i < N_NODES; i += stride) {
        if (i == 0 || batch[i] != batch[i - 1]) g_seg[batch[i]] = i;
    }
}

__global__ void scatter_kernel(const int* __restrict__ ei,
                               const int* __restrict__ xids,
                               const float* __restrict__ emb) {
    int warp = (blockIdx.x * blockDim.x + threadIdx.x) >> 5;
    int lane = threadIdx.x & 31;
    if (warp >= N_EDGES) return;
    int src = __ldg(ei + warp);
    int dst = __ldg(ei + N_EDGES + warp);
    int id  = __ldg(xids + src);
    const float4* row = reinterpret_cast<const float4*>(emb + (size_t)id * DIM);
    float4 v = __ldg(row + lane);
    float* outp = g_agg + (size_t)dst * DIM + lane * 4;
    asm volatile("red.global.add.v4.f32 [%0], {%1,%2,%3,%4};"
                 :: "l"(outp), "f"(v.x), "f"(v.y), "f"(v.z), "f"(v.w)
                 : "memory");
    if (lane == 0) atomicAdd(g_deg + dst, 1.0f);
}

// ---------------------------------------------------------------------------
// K3: warp-MMA GEMM, M=64 tiles, 2 blocks/SM for phase overlap.
// 4 warps: warp w owns rows w*16..w*16+15 x all 128 cols. Bias+relu applied
// in-place on accumulators; pooling via masked butterfly shuffle over the 8
// lanes sharing a column group, then per-(graph,col) atomics. No h tile.
// ---------------------------------------------------------------------------
__global__ void __launch_bounds__(128, 2)
mma_kernel(const int* __restrict__ xids,
           const int* __restrict__ batch,
           const float* __restrict__ emb,
           const float* __restrict__ Wl,
           const float* __restrict__ bl,
           const float* __restrict__ Wr) {
    extern __shared__ char dyn[];
    char* sW = dyn + OFF_W;            // [128 n][256 k] bf16, row stride 528B
    char* sA = dyn + OFF_A;            // [64 m][256 k] bf16, row stride 528B

    __shared__ float s_bl[DIM];
    __shared__ int   s_bid[TILE_M];

    const int t    = threadIdx.x;
    const int wid  = t >> 5;
    const int lane = t & 31;

    if (t < DIM) s_bl[t] = bl[t];

    // Stage combined weights [Wl | Wr] (once per block)
    for (int j = 0; j < 32; j++) {
        int chunk = t + j * 128;
        int n  = chunk >> 5;             // output column 0..127
        int ck = (chunk & 31) * 8;       // k chunk start (0..248)
        const float* src = (ck < DIM) ? (Wl + n * DIM + ck)
                                      : (Wr + n * DIM + (ck - DIM));
        float f[8];
        *reinterpret_cast<float4*>(f)     = *reinterpret_cast<const float4*>(src);
        *reinterpret_cast<float4*>(f + 4) = *reinterpret_cast<const float4*>(src + 4);
        *reinterpret_cast<uint4*>(sW + n * ROWB + ck * 2) = pack_bf16x8(f);
    }

    const uint32_t sA_base = smem_u32(sA);
    const uint32_t sW_base = smem_u32(sW);
    const uint32_t a_lane_off = (uint32_t)((wid * 16 + (lane & 15)) * ROWB
                                           + ((lane >> 4) * 8) * 2);
    const uint32_t b_lane_off = (uint32_t)((lane & 7) * ROWB
                                           + ((lane >> 3) & 1) * 16);

    for (int tile = blockIdx.x; tile < N_TILES; tile += GRID_GEMM) {
        const int tbase  = tile * TILE_M;
        const int nvalid = min(TILE_M, N_NODES - tbase);

        // ---- stage A tile: [aggn | x] -> bf16 (zero-fill pad rows) ----
        for (int j = 0; j < 16; j++) {
            int chunk = t + j * 128;
            int r  = chunk >> 5;             // 0..63
            int ck = (chunk & 31) * 8;
            int n  = tbase + r;
            float f[8];
#pragma unroll
            for (int i = 0; i < 8; i++) f[i] = 0.f;
            if (n < N_NODES) {
                if (ck < DIM) {
                    float sc = __fdividef(1.f, fmaxf(g_deg[n], 1.f));
                    const float4* s4 = reinterpret_cast<const float4*>(
                        g_agg + (size_t)n * DIM + ck);
                    *reinterpret_cast<float4*>(f)     = s4[0];
                    *reinterpret_cast<float4*>(f + 4) = s4[1];
#pragma unroll
                    for (int i = 0; i < 8; i++) f[i] *= sc;
                } else {
                    int id = __ldg(xids + n);
                    const float4* s4 = reinterpret_cast<const float4*>(
                        emb + (size_t)id * DIM + (ck - DIM));
                    *reinterpret_cast<float4*>(f)     = s4[0];
                    *reinterpret_cast<float4*>(f + 4) = s4[1];
                }
            }
            *reinterpret_cast<uint4*>(sA + r * ROWB + ck * 2) = pack_bf16x8(f);
        }
        if (t < TILE_M)
            s_bid[t] = (tbase + t < N_NODES) ? batch[tbase + t] : -1;
        __syncthreads();

        // ---- MMA mainloop: 16 k16 steps x 16 n-tiles ----
        float acc[16][4];
#pragma unroll
        for (int n = 0; n < 16; n++)
#pragma unroll
            for (int i = 0; i < 4; i++) acc[n][i] = 0.f;

        for (int kk = 0; kk < 16; kk++) {
            uint32_t a[4];
            ldsm_x4(a, sA_base + a_lane_off + kk * 32);
            uint32_t bf[16][2];
#pragma unroll
            for (int n = 0; n < 16; n++)
                ldsm_x2(bf[n], sW_base + (uint32_t)(n * 8 * ROWB) + b_lane_off
                               + kk * 32);
#pragma unroll
            for (int n = 0; n < 16; n++)
                mma16816(acc[n], a, bf[n]);
        }

        // ---- bias + relu in place ----
#pragma unroll
        for (int n = 0; n < 16; n++) {
            int c0 = n * 8 + (lane & 3) * 2;
            float b0 = s_bl[c0], b1 = s_bl[c0 + 1];
            acc[n][0] = fmaxf(acc[n][0] + b0, 0.f);
            acc[n][1] = fmaxf(acc[n][1] + b1, 0.f);
            acc[n][2] = fmaxf(acc[n][2] + b0, 0.f);
            acc[n][3] = fmaxf(acc[n][3] + b1, 0.f);
        }

        // ---- register pooling: masked butterfly over 8 row-lanes ----
        {
            const int q     = lane >> 2;
            const int strip = wid * 16;
            const int r_hi  = min(strip + 15, nvalid - 1);
            if (r_hi >= strip) {
                const int gid0 = s_bid[strip + q];       // row strip+q
                const int gid1 = s_bid[strip + q + 8];   // row strip+q+8 (-1 if pad)
                const int g0 = s_bid[strip];
                const int g1 = s_bid[r_hi];
                for (int g = g0; g <= g1; g++) {
                    bool in0 = (gid0 == g), in1 = (gid1 == g);
#pragma unroll
                    for (int n = 0; n < 16; n++) {
                        float a0 = in0 ? acc[n][0] : 0.f;
                        float a1 = in0 ? acc[n][1] : 0.f;
                        float a2 = in1 ? acc[n][2] : 0.f;
                        float a3 = in1 ? acc[n][3] : 0.f;
                        float mx0 = fmaxf(a0, a2), mx1 = fmaxf(a1, a3);
                        float sm0 = a0 + a2,       sm1 = a1 + a3;
#pragma unroll
                        for (int o = 4; o <= 16; o <<= 1) {
                            mx0 = fmaxf(mx0, __shfl_xor_sync(0xFFFFFFFFu, mx0, o));
                            mx1 = fmaxf(mx1, __shfl_xor_sync(0xFFFFFFFFu, mx1, o));
                            sm0 += __shfl_xor_sync(0xFFFFFFFFu, sm0, o);
                            sm1 += __shfl_xor_sync(0xFFFFFFFFu, sm1, o);
                        }
                        if (q == (n & 7)) {
                            int c0 = n * 8 + (lane & 3) * 2;
                            // h >= 0: int-compare atomicMax order-preserving
                            atomicMax(reinterpret_cast<int*>(&g_pmax[g * DIM + c0]),
                                      __float_as_int(mx0));
                            atomicMax(reinterpret_cast<int*>(&g_pmax[g * DIM + c0 + 1]),
                                      __float_as_int(mx1));
                            atomicAdd(&g_psum[g * DIM + c0], sm0);
                            atomicAdd(&g_psum[g * DIM + c0 + 1], sm1);
                        }
                    }
                }
            }
        }
        __syncthreads();   // sA/s_bid reuse safe for next tile
    }
}

// ---------------------------------------------------------------------------
__global__ void __launch_bounds__(128)
final_kernel(const float* __restrict__ w1, const float* __restrict__ b1,
             float* __restrict__ out) {
    __shared__ float sred[4];
    const int g = blockIdx.x;
    const int c = threadIdx.x;
    const int start = g_seg[g];
    const int end   = (g == NUM_GRAPHS - 1) ? N_NODES : g_seg[g + 1];
    const float cnt = (float)(end - start);
    float val = g_pmax[g * DIM + c] * w1[c]
              + (g_psum[g * DIM + c] / cnt) * w1[DIM + c];
#pragma unroll
    for (int off = 16; off > 0; off >>= 1)
        val += __shfl_down_sync(0xFFFFFFFFu, val, off);
    if ((c & 31) == 0) sred[c >> 5] = val;
    __syncthreads();
    if (c == 0) {
        float tot = sred[0] + sred[1] + sred[2] + sred[3] + b1[0];
        out[g] = 1.f / (1.f + expf(-tot));
    }
}

// ---------------------------------------------------------------------------
extern "C" void kernel_launch(void* const* d_in, const int* in_sizes, int n_in,
                              void* d_out, int out_size) {
    const int*   xids  = (const int*)d_in[0];
    const int*   ei    = (const int*)d_in[1];
    const int*   batch = (const int*)d_in[2];
    const float* emb   = (const float*)d_in[3];
    const float* Wl    = (const float*)d_in[4];
    const float* bl    = (const float*)d_in[5];
    const float* Wr    = (const float*)d_in[6];
    const float* w1    = (const float*)d_in[7];
    const float* b1    = (const float*)d_in[8];
    float*       out   = (float*)d_out;

    zero_kernel<<<2048, 256>>>();
    seg_kernel<<<256, 256>>>(batch);
    {
        long long threads = (long long)N_EDGES * 32;
        int blocks = (int)((threads + 255) / 256);
        scatter_kernel<<<blocks, 256>>>(ei, xids, emb);
    }
    static int attr_set = 0;
    if (!attr_set) {
        cudaFuncSetAttribute(mma_kernel,
                             cudaFuncAttributeMaxDynamicSharedMemorySize, SMEM_DYN);
        attr_set = 1;
    }
    mma_kernel<<<GRID_GEMM, 128, SMEM_DYN>>>(xids, batch, emb, Wl, bl, Wr);
    final_kernel<<<NUM_GRAPHS, 128>>>(w1, b1, out);
}

// round 13
// speedup vs baseline: 2.8644x; 1.1853x over previous
#include <cuda_runtime.h>
#include <cuda_bf16.h>
#include <math.h>
#include <stdint.h>

#define N_NODES    50000
#define N_EDGES    600000
#define DIM        128
#define VOCAB      20215
#define NUM_GRAPHS 512
#define PTILES     ((VOCAB + 63) / 64)     // 316
#define ROWB2      272                     // 128 bf16 = 256B + 16 pad; LDSM conflict-free
#define P_OFF_W    0                       // 256 x 272 = 69632
#define P_OFF_A    69632                   // 64 x 272  = 17408
#define P_SMEM     (69632 + 17408)

// Scratch (device globals: allocation inside kernel_launch is forbidden)
__device__ __align__(16) float g_agg[N_NODES * DIM];
__device__ __align__(16) float g_embWl[VOCAB * DIM];
__device__ __align__(16) float g_embWr[VOCAB * DIM];
__device__ float g_deg[N_NODES];
__device__ int   g_seg[NUM_GRAPHS];

// ---- warp-MMA helpers (sm_80-era PTX, valid for compute_100) ---------------
__device__ __forceinline__ uint32_t smem_u32(const void* p) {
    uint32_t a;
    asm("{ .reg .u64 t; cvta.to.shared.u64 t, %1; cvt.u32.u64 %0, t; }"
        : "=r"(a) : "l"(p));
    return a;
}
__device__ __forceinline__ void ldsm_x4(uint32_t* r, uint32_t addr) {
    asm volatile("ldmatrix.sync.aligned.m8n8.x4.shared.b16 {%0,%1,%2,%3}, [%4];"
                 : "=r"(r[0]), "=r"(r[1]), "=r"(r[2]), "=r"(r[3]) : "r"(addr));
}
__device__ __forceinline__ void ldsm_x2(uint32_t* r, uint32_t addr) {
    asm volatile("ldmatrix.sync.aligned.m8n8.x2.shared.b16 {%0,%1}, [%2];"
                 : "=r"(r[0]), "=r"(r[1]) : "r"(addr));
}
__device__ __forceinline__ void mma16816(float* c, const uint32_t* a, const uint32_t* b) {
    asm volatile(
        "mma.sync.aligned.m16n8k16.row.col.f32.bf16.bf16.f32 "
        "{%0,%1,%2,%3}, {%4,%5,%6,%7}, {%8,%9}, {%0,%1,%2,%3};"
        : "+f"(c[0]), "+f"(c[1]), "+f"(c[2]), "+f"(c[3])
        : "r"(a[0]), "r"(a[1]), "r"(a[2]), "r"(a[3]), "r"(b[0]), "r"(b[1]));
}
__device__ __forceinline__ uint4 pack_bf16x8(const float* f) {
    __nv_bfloat162 h0 = __float22bfloat162_rn(make_float2(f[0], f[1]));
    __nv_bfloat162 h1 = __float22bfloat162_rn(make_float2(f[2], f[3]));
    __nv_bfloat162 h2 = __float22bfloat162_rn(make_float2(f[4], f[5]));
    __nv_bfloat162 h3 = __float22bfloat162_rn(make_float2(f[6], f[7]));
    uint4 u;
    u.x = *reinterpret_cast<uint32_t*>(&h0);
    u.y = *reinterpret_cast<uint32_t*>(&h1);
    u.z = *reinterpret_cast<uint32_t*>(&h2);
    u.w = *reinterpret_cast<uint32_t*>(&h3);
    return u;
}

// ---------------------------------------------------------------------------
__global__ void zero_kernel() {
    int i = blockIdx.x * blockDim.x + threadIdx.x;
    int stride = gridDim.x * blockDim.x;
    float4* p = reinterpret_cast<float4*>(g_agg);
    const int n4 = N_NODES * DIM / 4;
    for (int k = i; k < n4; k += stride) p[k] = make_float4(0.f, 0.f, 0.f, 0.f);
    for (int k = i; k < N_NODES; k += stride) g_deg[k] = 0.f;
}

__global__ void seg_kernel(const int* __restrict__ batch) {
    int i = blockIdx.x * blockDim.x + threadIdx.x;
    int stride = gridDim.x * blockDim.x;
    for (; i < N_NODES; i += stride) {
        if (i == 0 || batch[i] != batch[i - 1]) g_seg[batch[i]] = i;
    }
}

// ---------------------------------------------------------------------------
// K2: precompute embWl = emb @ Wl^T, embWr = emb @ Wr^T (bf16 warp-MMA).
// One 64-row tile of emb per block vs the combined 256-col [Wl; Wr] weight.
// ---------------------------------------------------------------------------
__global__ void __launch_bounds__(128, 1)
precompute_kernel(const float* __restrict__ emb,
                  const float* __restrict__ Wl,
                  const float* __restrict__ Wr) {
    extern __shared__ char dyn[];
    char* sW = dyn + P_OFF_W;            // [256 n][128 k] bf16, stride 272B
    char* sA = dyn + P_OFF_A;            // [64 v][128 k] bf16, stride 272B

    const int t    = threadIdx.x;
    const int wid  = t >> 5;
    const int lane = t & 31;

    // Stage W' = [Wl; Wr]: 256 rows x 128 k
    for (int j = 0; j < 32; j++) {
        int chunk = t + j * 128;
        int n  = chunk >> 4;             // 0..255
        int ck = (chunk & 15) * 8;       // 0..120
        const float* src = (n < DIM) ? (Wl + n * DIM + ck)
                                     : (Wr + (n - DIM) * DIM + ck);
        float f[8];
        *reinterpret_cast<float4*>(f)     = *reinterpret_cast<const float4*>(src);
        *reinterpret_cast<float4*>(f + 4) = *reinterpret_cast<const float4*>(src + 4);
        *reinterpret_cast<uint4*>(sW + n * ROWB2 + ck * 2) = pack_bf16x8(f);
    }

    const int tbase = blockIdx.x * 64;
    // Stage A: emb rows tbase..tbase+63 (zero-pad past VOCAB)
    for (int j = 0; j < 8; j++) {
        int chunk = t + j * 128;
        int r  = chunk >> 4;             // 0..63
        int ck = (chunk & 15) * 8;
        int v  = tbase + r;
        float f[8];
#pragma unroll
        for (int i = 0; i < 8; i++) f[i] = 0.f;
        if (v < VOCAB) {
            const float4* s4 = reinterpret_cast<const float4*>(
                emb + (size_t)v * DIM + ck);
            *reinterpret_cast<float4*>(f)     = s4[0];
            *reinterpret_cast<float4*>(f + 4) = s4[1];
        }
        *reinterpret_cast<uint4*>(sA + r * ROWB2 + ck * 2) = pack_bf16x8(f);
    }
    __syncthreads();

    const uint32_t sA_base = smem_u32(sA);
    const uint32_t sW_base = smem_u32(sW);
    const uint32_t a_lane_off = (uint32_t)((wid * 16 + (lane & 15)) * ROWB2
                                           + ((lane >> 4) * 8) * 2);
    const uint32_t b_lane_off = (uint32_t)((lane & 7) * ROWB2
                                           + ((lane >> 3) & 1) * 16);

    float acc[32][4];
#pragma unroll
    for (int n = 0; n < 32; n++)
#pragma unroll
        for (int i = 0; i < 4; i++) acc[n][i] = 0.f;

    for (int kk = 0; kk < 8; kk++) {
        uint32_t a[4];
        ldsm_x4(a, sA_base + a_lane_off + kk * 32);
#pragma unroll
        for (int n = 0; n < 32; n++) {
            uint32_t b[2];
            ldsm_x2(b, sW_base + (uint32_t)(n * 8 * ROWB2) + b_lane_off + kk * 32);
            mma16816(acc[n], a, b);
        }
    }

    // Write out fp32: cols 0..127 -> embWl, 128..255 -> embWr
    const int row = wid * 16 + (lane >> 2);
    const int v0 = tbase + row;
    const int v1 = v0 + 8;
#pragma unroll
    for (int n = 0; n < 32; n++) {
        int col = (n & 15) * 8 + (lane & 3) * 2;
        float* dst = (n < 16) ? g_embWl : g_embWr;
        if (v0 < VOCAB)
            *reinterpret_cast<float2*>(dst + (size_t)v0 * DIM + col) =
                make_float2(acc[n][0], acc[n][1]);
        if (v1 < VOCAB)
            *reinterpret_cast<float2*>(dst + (size_t)v1 * DIM + col) =
                make_float2(acc[n][2], acc[n][3]);
    }
}

// ---------------------------------------------------------------------------
// K3: edge scatter of PRE-MULTIPLIED rows: agg[dst] += embWl[x_ids[src]].
// (Linearity: (sum x)/deg @ Wl^T == sum embWl[x] / deg.)
// ---------------------------------------------------------------------------
__global__ void scatter_kernel(const int* __restrict__ ei,
                               const int* __restrict__ xids) {
    int warp = (blockIdx.x * blockDim.x + threadIdx.x) >> 5;
    int lane = threadIdx.x & 31;
    if (warp >= N_EDGES) return;
    int src = __ldg(ei + warp);
    int dst = __ldg(ei + N_EDGES + warp);
    int id  = __ldg(xids + src);
    const float4* row = reinterpret_cast<const float4*>(g_embWl + (size_t)id * DIM);
    float4 v = __ldg(row + lane);
    float* outp = g_agg + (size_t)dst * DIM + lane * 4;
    asm volatile("red.global.add.v4.f32 [%0], {%1,%2,%3,%4};"
                 :: "l"(outp), "f"(v.x), "f"(v.y), "f"(v.z), "f"(v.w)
                 : "memory");
    if (lane == 0) atomicAdd(g_deg + dst, 1.0f);
}

// ---------------------------------------------------------------------------
// K4: fused pool: h = relu(agg/deg + embWr[id] + bl), per-graph max/mean,
// final 256-dot + sigmoid. One block (128 thr) per graph; thread c = column.
// All loads warp-coalesced (consecutive c) or broadcast (deg/xids).
// ---------------------------------------------------------------------------
__global__ void __launch_bounds__(128)
pool_kernel(const int* __restrict__ xids,
            const float* __restrict__ bl,
            const float* __restrict__ w1,
            const float* __restrict__ b1,
            float* __restrict__ out) {
    __shared__ float sred[4];
    const int g = blockIdx.x;
    const int c = threadIdx.x;
    const int start = g_seg[g];
    const int end   = (g == NUM_GRAPHS - 1) ? N_NODES : g_seg[g + 1];
    const float cnt = (float)(end - start);
    const float blc = bl[c];

    float maxj = 0.f, sumj = 0.f;   // relu >= 0: 0 is valid max identity
    int n = start;
    for (; n + 4 <= end; n += 4) {
        float a[4], e[4], d[4];
#pragma unroll
        for (int m = 0; m < 4; m++) {
            int nn = n + m;
            a[m] = g_agg[(size_t)nn * DIM + c];
            e[m] = g_embWr[(size_t)__ldg(xids + nn) * DIM + c];
            d[m] = g_deg[nn];
        }
#pragma unroll
        for (int m = 0; m < 4; m++) {
            float sc = __fdividef(1.f, fmaxf(d[m], 1.f));
            float hv = fmaxf(fmaf(a[m], sc, e[m]) + blc, 0.f);
            maxj = fmaxf(maxj, hv);
            sumj += hv;
        }
    }
    for (; n < end; n++) {
        float sc = __fdividef(1.f, fmaxf(g_deg[n], 1.f));
        float hv = fmaxf(fmaf(g_agg[(size_t)n * DIM + c], sc,
                              g_embWr[(size_t)__ldg(xids + n) * DIM + c]) + blc,
                         0.f);
        maxj = fmaxf(maxj, hv);
        sumj += hv;
    }

    float val = maxj * w1[c] + (sumj / cnt) * w1[DIM + c];
#pragma unroll
    for (int off = 16; off > 0; off >>= 1)
        val += __shfl_down_sync(0xFFFFFFFFu, val, off);
    if ((c & 31) == 0) sred[c >> 5] = val;
    __syncthreads();
    if (c == 0) {
        float tot = sred[0] + sred[1] + sred[2] + sred[3] + b1[0];
        out[g] = 1.f / (1.f + expf(-tot));
    }
}

// ---------------------------------------------------------------------------
extern "C" void kernel_launch(void* const* d_in, const int* in_sizes, int n_in,
                              void* d_out, int out_size) {
    const int*   xids  = (const int*)d_in[0];
    const int*   ei    = (const int*)d_in[1];
    const int*   batch = (const int*)d_in[2];
    const float* emb   = (const float*)d_in[3];
    const float* Wl    = (const float*)d_in[4];
    const float* bl    = (const float*)d_in[5];
    const float* Wr    = (const float*)d_in[6];
    const float* w1    = (const float*)d_in[7];
    const float* b1    = (const float*)d_in[8];
    float*       out   = (float*)d_out;

    zero_kernel<<<2048, 256>>>();
    seg_kernel<<<256, 256>>>(batch);
    static int attr_set = 0;
    if (!attr_set) {
        cudaFuncSetAttribute(precompute_kernel,
                             cudaFuncAttributeMaxDynamicSharedMemorySize, P_SMEM);
        attr_set = 1;
    }
    precompute_kernel<<<PTILES, 128, P_SMEM>>>(emb, Wl, Wr);
    {
        long long threads = (long long)N_EDGES * 32;
        int blocks = (int)((threads + 255) / 256);
        scatter_kernel<<<blocks, 256>>>(ei, xids);
    }
    pool_kernel<<<NUM_GRAPHS, 128>>>(xids, bl, w1, b1, out);
}